// round 6
// baseline (speedup 1.0000x reference)
#include <cuda_runtime.h>
#include <math.h>

#define Bn 16
#define Cn 2048
#define Ln 256
#define EO 16
#define Hn 4
#define Gn 4
#define Nn (Bn*Cn)      /* 32768 */
#define NEn 524288

typedef unsigned long long ull;

// ---------------- scratch (device globals; no allocation) ----------------
__device__ __align__(16) float g_y[Nn*EO];        // emb output (incl emb_b)
__device__ __align__(16) float g_G[Bn*EO*EO];     // gatW * s  per batch
__device__ __align__(16) float g_fe[Nn*20];       // per node: feat[16] + el[4]
__device__ __align__(16) float g_er[Nn*Hn];
__device__ __align__(16) float g_enc[Nn*EO];
__device__ float g_pa[Nn];
__device__ float g_pb[Nn];
__device__ int   g_cnt[Nn];                       // in-degree
__device__ int   g_off[Nn];                       // CSR start
__device__ int   g_cur[Nn];                       // scatter cursor
__device__ int   g_eidx[NEn];                     // src ids sorted by dst

// ---------------- f32x2 helpers ----------------
__device__ __forceinline__ ull pack2(float lo, float hi){
    ull r; asm("mov.b64 %0, {%1, %2};" : "=l"(r) : "f"(lo), "f"(hi)); return r;
}
__device__ __forceinline__ void unpack2(ull v, float& lo, float& hi){
    asm("mov.b64 {%0, %1}, %2;" : "=f"(lo), "=f"(hi) : "l"(v));
}
__device__ __forceinline__ ull ffma2(ull a, ull b, ull c){
    ull d; asm("fma.rn.f32x2 %0, %1, %2, %3;" : "=l"(d) : "l"(a), "l"(b), "l"(c)); return d;
}
union F4U { float4 v; ull u[2]; };

// ---------------- zero in-degree counters ----------------
__global__ void k_init(){
    g_cnt[blockIdx.x*256 + threadIdx.x] = 0;
}

// ---------------- y = feature @ embW^T + emb_b : one thread per node ----------------
__global__ void __launch_bounds__(128) k_emb(const float* __restrict__ feature,
                                             const float* __restrict__ embW,
                                             const float* __restrict__ embB){
    __shared__ __align__(16) float sW[Ln*EO];     // k-major: sW[k*16+e]
    int tid = threadIdx.x;
    for(int idx = tid; idx < Ln*EO; idx += 128){
        int e = idx >> 8, k = idx & 255;
        sW[k*16 + e] = embW[e*Ln + k];
    }
    __syncthreads();

    int n = blockIdx.x*128 + tid;
    const float4* fp = (const float4*)(feature + (size_t)n*Ln);

    ull acc2[8];
    #pragma unroll
    for(int g=0; g<8; g++) acc2[g] = 0ull;

    #pragma unroll 4
    for(int j=0; j<64; j++){
        float4 f = fp[j];
        float fv[4] = {f.x, f.y, f.z, f.w};
        #pragma unroll
        for(int i=0; i<4; i++){
            ull fd = pack2(fv[i], fv[i]);
            const float* wk = sW + (j*4+i)*16;
            F4U w0, w1, w2, w3;
            w0.v = *(const float4*)(wk);
            w1.v = *(const float4*)(wk+4);
            w2.v = *(const float4*)(wk+8);
            w3.v = *(const float4*)(wk+12);
            acc2[0] = ffma2(fd, w0.u[0], acc2[0]);
            acc2[1] = ffma2(fd, w0.u[1], acc2[1]);
            acc2[2] = ffma2(fd, w1.u[0], acc2[2]);
            acc2[3] = ffma2(fd, w1.u[1], acc2[3]);
            acc2[4] = ffma2(fd, w2.u[0], acc2[4]);
            acc2[5] = ffma2(fd, w2.u[1], acc2[5]);
            acc2[6] = ffma2(fd, w3.u[0], acc2[6]);
            acc2[7] = ffma2(fd, w3.u[1], acc2[7]);
        }
    }
    float acc[16];
    #pragma unroll
    for(int g=0; g<8; g++) unpack2(acc2[g], acc[2*g], acc[2*g+1]);
    float4* yo = (float4*)&g_y[(size_t)n*EO];
    yo[0] = make_float4(acc[0]+__ldg(&embB[0]),  acc[1]+__ldg(&embB[1]),
                        acc[2]+__ldg(&embB[2]),  acc[3]+__ldg(&embB[3]));
    yo[1] = make_float4(acc[4]+__ldg(&embB[4]),  acc[5]+__ldg(&embB[5]),
                        acc[6]+__ldg(&embB[6]),  acc[7]+__ldg(&embB[7]));
    yo[2] = make_float4(acc[8]+__ldg(&embB[8]),  acc[9]+__ldg(&embB[9]),
                        acc[10]+__ldg(&embB[10]),acc[11]+__ldg(&embB[11]));
    yo[3] = make_float4(acc[12]+__ldg(&embB[12]),acc[13]+__ldg(&embB[13]),
                        acc[14]+__ldg(&embB[14]),acc[15]+__ldg(&embB[15]));
}

// ---------------- per batch: z = mean(y), SE -> s, G_b = gatW * s ----------------
__global__ void k_zprep(const float* __restrict__ w1, const float* __restrict__ b1,
                        const float* __restrict__ w2, const float* __restrict__ b2,
                        const float* __restrict__ gatW){
    int b = blockIdx.x, t = threadIdx.x;
    __shared__ float sred[16*17];
    __shared__ float zs[16], r1[4], ss[16];
    int e = t & 15, part = t >> 4;
    const float* yp = g_y + ((size_t)b*Cn + part)*EO + e;
    float a = 0.f;
    for(int j=0; j<128; j++) a += yp[(size_t)j*16*EO];
    sred[part*17 + e] = a;
    __syncthreads();
    if(t < 16){
        float s2 = 0.f;
        #pragma unroll
        for(int p=0; p<16; p++) s2 += sred[p*17 + t];
        zs[t] = s2 * (1.0f/Cn);
    }
    __syncthreads();
    if(t < 4){
        float a1 = b1[t];
        #pragma unroll
        for(int ee=0; ee<16; ee++) a1 = fmaf(w1[t*16+ee], zs[ee], a1);
        r1[t] = fmaxf(a1, 0.f);
    }
    __syncthreads();
    if(t < 16){
        float a2 = b2[t];
        #pragma unroll
        for(int j=0; j<4; j++) a2 = fmaf(w2[t*4+j], r1[j], a2);
        ss[t] = 1.f/(1.f + __expf(-a2));
    }
    __syncthreads();
    g_G[b*256 + t] = gatW[t] * ss[t & 15];
}

// ---------------- feat = y_s @ gatW^T ; el -> g_fe, er -> g_er ----------------
__global__ void __launch_bounds__(256) k_feat2(const float* __restrict__ al,
                                               const float* __restrict__ ar){
    __shared__ float sG[256];
    __shared__ float sal[16], sar[16];
    int t = threadIdx.x;
    int nb = blockIdx.x*256;
    int b = nb >> 11;
    sG[t] = g_G[b*256 + t];
    if(t < 16){ sal[t]=al[t]; sar[t]=ar[t]; }
    __syncthreads();

    int n = nb + t;
    const float4* yp = (const float4*)&g_y[(size_t)n*EO];
    float4 y0=yp[0], y1=yp[1], y2=yp[2], y3=yp[3];
    float yv[16] = {y0.x,y0.y,y0.z,y0.w, y1.x,y1.y,y1.z,y1.w,
                    y2.x,y2.y,y2.z,y2.w, y3.x,y3.y,y3.z,y3.w};
    float fe[16];
    #pragma unroll
    for(int hd=0; hd<16; hd++){
        const float4* gp = (const float4*)(sG + hd*16);
        float4 g0=gp[0], g1=gp[1], g2=gp[2], g3=gp[3];
        float a = 0.f;
        a = fmaf(g0.x,yv[0],a);  a = fmaf(g0.y,yv[1],a);
        a = fmaf(g0.z,yv[2],a);  a = fmaf(g0.w,yv[3],a);
        a = fmaf(g1.x,yv[4],a);  a = fmaf(g1.y,yv[5],a);
        a = fmaf(g1.z,yv[6],a);  a = fmaf(g1.w,yv[7],a);
        a = fmaf(g2.x,yv[8],a);  a = fmaf(g2.y,yv[9],a);
        a = fmaf(g2.z,yv[10],a); a = fmaf(g2.w,yv[11],a);
        a = fmaf(g3.x,yv[12],a); a = fmaf(g3.y,yv[13],a);
        a = fmaf(g3.z,yv[14],a); a = fmaf(g3.w,yv[15],a);
        fe[hd] = a;
    }
    float4* fo = (float4*)&g_fe[(size_t)n*20];
    fo[0] = make_float4(fe[0],fe[1],fe[2],fe[3]);
    fo[1] = make_float4(fe[4],fe[5],fe[6],fe[7]);
    fo[2] = make_float4(fe[8],fe[9],fe[10],fe[11]);
    fo[3] = make_float4(fe[12],fe[13],fe[14],fe[15]);
    float el[4], er[4];
    #pragma unroll
    for(int h=0; h<4; h++){
        float a=0.f, c=0.f;
        #pragma unroll
        for(int d=0; d<4; d++){
            a = fmaf(fe[h*4+d], sal[h*4+d], a);
            c = fmaf(fe[h*4+d], sar[h*4+d], c);
        }
        el[h]=a; er[h]=c;
    }
    fo[4] = make_float4(el[0],el[1],el[2],el[3]);
    *(float4*)&g_er[n*4] = make_float4(er[0],er[1],er[2],er[3]);
}

// ---------------- CSR build: histogram ----------------
__global__ void k_hist(const int* __restrict__ dst){
    int i = blockIdx.x*256 + threadIdx.x;
    int4 d = ((const int4*)dst)[i];
    atomicAdd(&g_cnt[d.x], 1);
    atomicAdd(&g_cnt[d.y], 1);
    atomicAdd(&g_cnt[d.z], 1);
    atomicAdd(&g_cnt[d.w], 1);
}

// ---------------- CSR build: exclusive scan (single block) ----------------
__global__ void __launch_bounds__(1024) k_scan(){
    __shared__ int ssum[1024];
    int t = threadIdx.x;
    int base = t*32;
    int tot = 0;
    for(int j=0; j<32; j++) tot += g_cnt[base+j];
    ssum[t] = tot;
    __syncthreads();
    for(int d=1; d<1024; d<<=1){
        int v = (t >= d) ? ssum[t-d] : 0;
        __syncthreads();
        ssum[t] += v;
        __syncthreads();
    }
    int run = ssum[t] - tot;    // exclusive prefix
    for(int j=0; j<32; j++){
        int c = g_cnt[base+j];
        g_off[base+j] = run;
        g_cur[base+j] = run;
        run += c;
    }
}

// ---------------- CSR build: scatter src by dst ----------------
__global__ void k_scatter(const int* __restrict__ src, const int* __restrict__ dst){
    int i = blockIdx.x*256 + threadIdx.x;
    int4 d = ((const int4*)dst)[i];
    int4 s = ((const int4*)src)[i];
    int p0 = atomicAdd(&g_cur[d.x], 1); g_eidx[p0] = s.x;
    int p1 = atomicAdd(&g_cur[d.y], 1); g_eidx[p1] = s.y;
    int p2 = atomicAdd(&g_cur[d.z], 1); g_eidx[p2] = s.z;
    int p3 = atomicAdd(&g_cur[d.w], 1); g_eidx[p3] = s.w;
}

// ---------------- warp-per-node aggregation + normalize + pa/pb ----------------
__global__ void __launch_bounds__(256) k_agg(const float* __restrict__ gatB,
                                             const float* __restrict__ projW,
                                             const float* __restrict__ projB,
                                             const float* __restrict__ graphW){
    __shared__ float sgb[16], spw[64], spb2[4], sgw[8];
    int t = threadIdx.x;
    if(t < 16) sgb[t] = gatB[t];
    if(t < 64) spw[t] = projW[t];
    if(t < 4)  spb2[t] = projB[t];
    if(t < 8)  sgw[t] = graphW[t];
    __syncthreads();

    int n    = (blockIdx.x*256 + t) >> 5;
    int lane = t & 31;
    int off  = g_off[n];
    int deg  = g_cnt[n];
    float4 er = *(const float4*)&g_er[n*4];

    float den[4] = {0.f,0.f,0.f,0.f};
    float acc[16];
    #pragma unroll
    for(int j=0; j<16; j++) acc[j] = 0.f;

    for(int base=0; base<deg; base+=32){
        int idx = base + lane;
        if(idx < deg){
            int s = g_eidx[off + idx];
            const float4* fp = (const float4*)&g_fe[(size_t)s*20];
            float4 f0=fp[0], f1=fp[1], f2=fp[2], f3=fp[3], el=fp[4];
            float v0=el.x+er.x, v1=el.y+er.y, v2=el.z+er.z, v3=el.w+er.w;
            v0 = v0>0.f?v0:0.2f*v0;  v1 = v1>0.f?v1:0.2f*v1;
            v2 = v2>0.f?v2:0.2f*v2;  v3 = v3>0.f?v3:0.2f*v3;
            float e0=__expf(v0), e1=__expf(v1), e2=__expf(v2), e3=__expf(v3);
            den[0]+=e0; den[1]+=e1; den[2]+=e2; den[3]+=e3;
            acc[0]+=e0*f0.x; acc[1]+=e0*f0.y; acc[2]+=e0*f0.z; acc[3]+=e0*f0.w;
            acc[4]+=e1*f1.x; acc[5]+=e1*f1.y; acc[6]+=e1*f1.z; acc[7]+=e1*f1.w;
            acc[8]+=e2*f2.x; acc[9]+=e2*f2.y; acc[10]+=e2*f2.z; acc[11]+=e2*f2.w;
            acc[12]+=e3*f3.x; acc[13]+=e3*f3.y; acc[14]+=e3*f3.z; acc[15]+=e3*f3.w;
        }
    }
    #pragma unroll
    for(int m=16; m; m>>=1){
        #pragma unroll
        for(int h=0; h<4; h++) den[h] += __shfl_xor_sync(0xffffffffu, den[h], m);
        #pragma unroll
        for(int j=0; j<16; j++) acc[j] += __shfl_xor_sync(0xffffffffu, acc[j], m);
    }
    if(lane == 0){
        float enc[16];
        #pragma unroll
        for(int h=0; h<4; h++){
            float inv = den[h] > 0.f ? 1.f/den[h] : 0.f;
            #pragma unroll
            for(int j=0; j<4; j++) enc[h*4+j] = acc[h*4+j]*inv + sgb[h*4+j];
        }
        float4* eo = (float4*)&g_enc[(size_t)n*EO];
        eo[0] = make_float4(enc[0],enc[1],enc[2],enc[3]);
        eo[1] = make_float4(enc[4],enc[5],enc[6],enc[7]);
        eo[2] = make_float4(enc[8],enc[9],enc[10],enc[11]);
        eo[3] = make_float4(enc[12],enc[13],enc[14],enc[15]);
        float pa=0.f, pb=0.f;
        #pragma unroll
        for(int g=0; g<Gn; g++){
            float hp = spb2[g];
            #pragma unroll
            for(int hd=0; hd<16; hd++) hp = fmaf(spw[g*16+hd], enc[hd], hp);
            pa = fmaf(hp, sgw[g],    pa);
            pb = fmaf(hp, sgw[Gn+g], pb);
        }
        g_pa[n]=pa; g_pb[n]=pb;
    }
}

// ---------------- final: out = w*gram + (1-w)*(pa_i+pb_j), batched w reuse ----------------
__global__ void __launch_bounds__(256,2) k_out(const float* __restrict__ w,
                                               float* __restrict__ out){
    __shared__ __align__(16) float sA[16*132];
    __shared__ __align__(16) float sB[16*132];
    __shared__ float spa[128], spb[128];
    int i0 = blockIdx.y*128, j0 = blockIdx.x*128;
    int t  = threadIdx.x;
    int tx = t & 15, ty = t >> 4;

    for(int bi=0; bi<4; bi++){
        int b = blockIdx.z*4 + bi;
        __syncthreads();
        const float* encA = &g_enc[((size_t)b*Cn + i0)*EO];
        const float* encB = &g_enc[((size_t)b*Cn + j0)*EO];
        for(int i=t; i<2048; i+=256){
            int k = i&15, r = i>>4;
            sA[k*132 + r] = encA[i];
            sB[k*132 + r] = encB[i];
        }
        if(t < 128){ spa[t] = g_pa[b*Cn + i0 + t]; spb[t] = g_pb[b*Cn + j0 + t]; }
        __syncthreads();

        ull acc2[8][4];
        #pragma unroll
        for(int u=0; u<8; u++)
            #pragma unroll
            for(int v=0; v<4; v++) acc2[u][v] = 0ull;

        #pragma unroll
        for(int k=0; k<16; k++){
            const float* Ap = sA + k*132 + (ty<<3);
            const float* Bp = sB + k*132 + (tx<<3);
            float4 a0 = *(const float4*)Ap, a1 = *(const float4*)(Ap+4);
            F4U b0, b1;
            b0.v = *(const float4*)Bp;  b1.v = *(const float4*)(Bp+4);
            float av[8] = {a0.x,a0.y,a0.z,a0.w, a1.x,a1.y,a1.z,a1.w};
            ull bp[4] = {b0.u[0], b0.u[1], b1.u[0], b1.u[1]};
            #pragma unroll
            for(int u=0; u<8; u++){
                ull ad = pack2(av[u], av[u]);
                acc2[u][0] = ffma2(ad, bp[0], acc2[u][0]);
                acc2[u][1] = ffma2(ad, bp[1], acc2[u][1]);
                acc2[u][2] = ffma2(ad, bp[2], acc2[u][2]);
                acc2[u][3] = ffma2(ad, bp[3], acc2[u][3]);
            }
        }

        float par[8], pbc[8];
        #pragma unroll
        for(int u=0; u<8; u++){ par[u]=spa[(ty<<3)+u]; pbc[u]=spb[(tx<<3)+u]; }

        const size_t ob = (size_t)b*Cn*Cn;
        #pragma unroll
        for(int u=0; u<8; u++){
            float acc[8];
            #pragma unroll
            for(int v=0; v<4; v++) unpack2(acc2[u][v], acc[2*v], acc[2*v+1]);
            int i = i0 + (ty<<3) + u;
            const float* wr = w + (size_t)i*Cn + j0 + (tx<<3);
            float4 w0=*(const float4*)wr, w1=*(const float4*)(wr+4);
            float g2;
            float4 o0, o1;
            g2=par[u]+pbc[0]; o0.x=fmaf(w0.x, acc[0]-g2, g2);
            g2=par[u]+pbc[1]; o0.y=fmaf(w0.y, acc[1]-g2, g2);
            g2=par[u]+pbc[2]; o0.z=fmaf(w0.z, acc[2]-g2, g2);
            g2=par[u]+pbc[3]; o0.w=fmaf(w0.w, acc[3]-g2, g2);
            g2=par[u]+pbc[4]; o1.x=fmaf(w1.x, acc[4]-g2, g2);
            g2=par[u]+pbc[5]; o1.y=fmaf(w1.y, acc[5]-g2, g2);
            g2=par[u]+pbc[6]; o1.z=fmaf(w1.z, acc[6]-g2, g2);
            g2=par[u]+pbc[7]; o1.w=fmaf(w1.w, acc[7]-g2, g2);
            float* orow = out + ob + (size_t)i*Cn + j0 + (tx<<3);
            *(float4*)orow     = o0;
            *(float4*)(orow+4) = o1;
        }
    }
}

// ---------------- launch ----------------
extern "C" void kernel_launch(void* const* d_in, const int* in_sizes, int n_in,
                              void* d_out, int out_size){
    const float* feature=(const float*)d_in[0];
    const int*   src    =(const int*)  d_in[1];
    const int*   dst    =(const int*)  d_in[2];
    const float* embW   =(const float*)d_in[3];
    const float* embB   =(const float*)d_in[4];
    const float* seW1   =(const float*)d_in[5];
    const float* seB1   =(const float*)d_in[6];
    const float* seW2   =(const float*)d_in[7];
    const float* seB2   =(const float*)d_in[8];
    const float* gatW   =(const float*)d_in[9];
    const float* al     =(const float*)d_in[10];
    const float* ar     =(const float*)d_in[11];
    const float* gatB   =(const float*)d_in[12];
    const float* projW  =(const float*)d_in[13];
    const float* projB  =(const float*)d_in[14];
    const float* graphW =(const float*)d_in[15];
    const float* wmat   =(const float*)d_in[16];
    float* out = (float*)d_out;

    k_init   <<<Nn/256, 256>>>();
    k_emb    <<<Nn/128, 128>>>(feature, embW, embB);
    k_zprep  <<<Bn, 256>>>(seW1, seB1, seW2, seB2, gatW);
    k_feat2  <<<Nn/256, 256>>>(al, ar);
    k_hist   <<<NEn/1024, 256>>>(dst);
    k_scan   <<<1, 1024>>>();
    k_scatter<<<NEn/1024, 256>>>(src, dst);
    k_agg    <<<Nn*32/256, 256>>>(gatB, projW, projB, graphW);
    k_out    <<<dim3(Cn/128, Cn/128, 4), 256>>>(wmat, out);
}